// round 8
// baseline (speedup 1.0000x reference)
#include <cuda_runtime.h>
#include <cuda_fp16.h>
#include <cstdint>

// Grouped GEMM, pure fp16 HMMA, fp32 accumulate.
// B kept in native [k][n] layout; fragments via ldmatrix.trans (no transpose pass).
// Tile 128x256, warp tile 64x64, BK=64, 3-stage cp.async, panel-swizzled CTAs.
// GEMM split into 4 launches (diagnostic: puts GEMM in the ncu capture slot; tail-neutral).

static constexpr int HIDDEN = 2048;
static constexpr int FFN    = 8192;
static constexpr int MTOTAL = 16384;
static constexpr int NGROUPS = 8;

#define BM 128
#define BN 256
#define BK 64
static constexpr int NCHUNK = HIDDEN / BK;   // 32

// A row: 64 fp16 (128B) + 16B pad = 144B. B row: 256 fp16 (512B) + 16B pad = 528B.
#define ROWA 144
#define ROWBB 528
#define OFF_A 0
#define OFF_B (BM * ROWA)                    // 18432
#define STAGE (OFF_B + BK * ROWBB)           // 52224
#define NSTAGE 3
#define SMEM_DYN (NSTAGE * STAGE)            // 156672

// ---- scratch ----
__device__ __half g_Ah[(size_t)MTOTAL * HIDDEN];
__device__ __half g_Wh[(size_t)NGROUPS * HIDDEN * FFN];   // [g][k][n] (native layout)

__constant__ int kGroupOff[9] = {0, 1024, 2560, 4608, 6656, 9216, 11264, 14336, 16384};

__device__ __forceinline__ uint32_t pack_h2(__half lo, __half hi) {
    return (uint32_t)__half_as_ushort(lo) | ((uint32_t)__half_as_ushort(hi) << 16);
}

// ================= conversions (both pure streaming) =================

__global__ void convA_kernel(const float* __restrict__ A, __half* __restrict__ Ah) {
    size_t i = ((size_t)blockIdx.x * blockDim.x + threadIdx.x) * 4;
    float4 v = *(const float4*)(A + i);
    ((uint32_t*)(Ah + i))[0] = pack_h2(__float2half(v.x), __float2half(v.y));
    ((uint32_t*)(Ah + i))[1] = pack_h2(__float2half(v.z), __float2half(v.w));
}

__global__ void convW_kernel(const float* __restrict__ W, __half* __restrict__ Wh) {
    size_t i = ((size_t)blockIdx.x * blockDim.x + threadIdx.x) * 4;
    float4 v = *(const float4*)(W + i);
    ((uint32_t*)(Wh + i))[0] = pack_h2(__float2half(v.x), __float2half(v.y));
    ((uint32_t*)(Wh + i))[1] = pack_h2(__float2half(v.z), __float2half(v.w));
}

// ================= GEMM =================

__device__ __forceinline__ uint32_t smem_u32(const void* p) {
    uint32_t a;
    asm("{ .reg .u64 t; cvta.to.shared.u64 t, %1; cvt.u32.u64 %0, t; }" : "=r"(a) : "l"(p));
    return a;
}
__device__ __forceinline__ void cp16(uint32_t dst, const void* src) {
    asm volatile("cp.async.cg.shared.global [%0], [%1], 16;\n"
                 :: "r"(dst), "l"(__cvta_generic_to_global(src)));
}
__device__ __forceinline__ void ldmx4(uint32_t* r, uint32_t addr) {
    asm volatile("ldmatrix.sync.aligned.m8n8.x4.shared.b16 {%0,%1,%2,%3}, [%4];"
                 : "=r"(r[0]), "=r"(r[1]), "=r"(r[2]), "=r"(r[3]) : "r"(addr));
}
__device__ __forceinline__ void ldmx4t(uint32_t* r, uint32_t addr) {
    asm volatile("ldmatrix.sync.aligned.m8n8.x4.trans.shared.b16 {%0,%1,%2,%3}, [%4];"
                 : "=r"(r[0]), "=r"(r[1]), "=r"(r[2]), "=r"(r[3]) : "r"(addr));
}
__device__ __forceinline__ void mma16816(float* c, const uint32_t* a, const uint32_t* b) {
    asm volatile(
        "mma.sync.aligned.m16n8k16.row.col.f32.f16.f16.f32 "
        "{%0,%1,%2,%3}, {%4,%5,%6,%7}, {%8,%9}, {%0,%1,%2,%3};"
        : "+f"(c[0]), "+f"(c[1]), "+f"(c[2]), "+f"(c[3])
        : "r"(a[0]), "r"(a[1]), "r"(a[2]), "r"(a[3]), "r"(b[0]), "r"(b[1]));
}

__global__ __launch_bounds__(256, 1)
void gemm_hmma_kernel(float* __restrict__ C, int bidOffset) {
    extern __shared__ char smem[];
    const uint32_t sb = smem_u32(smem);

    const int tid  = threadIdx.x;
    const int warp = tid >> 5;
    const int lane = tid & 31;
    const int warpM = warp & 1;      // 0..1 -> M offset *64
    const int warpN = warp >> 1;     // 0..3 -> N offset *64

    // panel swizzle on global bid
    const int bid   = bidOffset + blockIdx.x;     // 0..4095
    const int panel = bid >> 9;
    const int idx   = bid & 511;
    const int rowBase = (panel * 16 + (idx & 15)) * BM;
    const int colBase = (idx >> 4) * BN;

    int g = 0;
#pragma unroll
    for (int i = 1; i < 8; ++i)
        if (rowBase >= kGroupOff[i]) g = i;

    const __half* pA = g_Ah + (size_t)rowBase * HIDDEN;
    const __half* pB = g_Wh + (size_t)g * HIDDEN * FFN + colBase;   // row k major

    // A copy slots: 128 rows x 8 chunks(16B) = 1024 -> 4/thread
    const int arow = tid >> 3;          // 0..31 (+32i)
    const int achk = tid & 7;           // 0..7
    const uint32_t soA = (uint32_t)(arow * ROWA + achk * 16);
    const size_t   goA = (size_t)arow * HIDDEN + achk * 8;
    // B copy slots: 64 k-rows x 32 chunks(16B) = 2048 -> 8/thread
    const int brow = tid >> 5;          // 0..7 (+8i)
    const int bchk = tid & 31;          // 0..31
    const uint32_t soB = (uint32_t)(brow * ROWBB + bchk * 16);
    const size_t   goB = (size_t)brow * FFN + bchk * 8;

    // ldmatrix offsets
    const uint32_t aOff = (uint32_t)((warpM * 64 + (lane & 15)) * ROWA + (lane >> 4) * 16);
    // B trans: row = k-in-step (lane&15), col = n0 + 8*(lane>>4)
    uint32_t bOff[4];
#pragma unroll
    for (int t = 0; t < 4; ++t)
        bOff[t] = (uint32_t)((lane & 15) * ROWBB
                             + (warpN * 64 + t * 16 + 8 * (lane >> 4)) * 2);

    float acc[4][8][4];
#pragma unroll
    for (int i = 0; i < 4; ++i)
#pragma unroll
        for (int n = 0; n < 8; ++n)
#pragma unroll
            for (int q = 0; q < 4; ++q) acc[i][n][q] = 0.0f;

#define ISSUE_LOADS(stagep, jj)                                                \
    do {                                                                       \
        const uint32_t st_ = (stagep);                                         \
        const size_t koA_ = (size_t)(jj) * BK;                                 \
        const size_t koB_ = (size_t)(jj) * BK * FFN;                           \
        _Pragma("unroll")                                                      \
        for (int i_ = 0; i_ < 4; ++i_)                                         \
            cp16(st_ + OFF_A + soA + i_ * 32 * ROWA,                           \
                 pA + goA + (size_t)i_ * 32 * HIDDEN + koA_);                  \
        _Pragma("unroll")                                                      \
        for (int i_ = 0; i_ < 8; ++i_)                                         \
            cp16(st_ + OFF_B + soB + i_ * 8 * ROWBB,                           \
                 pB + goB + (size_t)i_ * 8 * FFN + koB_);                      \
    } while (0)

    // prologue: stages 0,1
#pragma unroll
    for (int j = 0; j < NSTAGE - 1; ++j) {
        ISSUE_LOADS(sb + j * STAGE, j);
        asm volatile("cp.async.commit_group;" ::: "memory");
    }

    for (int j = 0; j < NCHUNK; ++j) {
        asm volatile("cp.async.wait_group %0;" :: "n"(NSTAGE - 2) : "memory");
        __syncthreads();

        if (j + NSTAGE - 1 < NCHUNK)
            ISSUE_LOADS(sb + ((j + NSTAGE - 1) % NSTAGE) * STAGE, j + NSTAGE - 1);
        asm volatile("cp.async.commit_group;" ::: "memory");

        const uint32_t st = sb + (j % NSTAGE) * STAGE;
#pragma unroll
        for (int s = 0; s < 4; ++s) {            // 4 k16-steps per BK=64 chunk
            uint32_t ah[4][4];
#pragma unroll
            for (int i = 0; i < 4; ++i)
                ldmx4(ah[i], st + OFF_A + aOff + i * 16 * ROWA + s * 32);
#pragma unroll
            for (int t = 0; t < 4; ++t) {
                uint32_t bh[4];
                ldmx4t(bh, st + OFF_B + bOff[t] + s * 16 * ROWBB);
#pragma unroll
                for (int i = 0; i < 4; ++i) {
                    mma16816(acc[i][2 * t],     ah[i], bh);
                    mma16816(acc[i][2 * t + 1], ah[i], bh + 2);
                }
            }
        }
    }
#undef ISSUE_LOADS

    // epilogue
    const int mBase = rowBase + warpM * 64;
    const int nBase = colBase + warpN * 64;
#pragma unroll
    for (int i = 0; i < 4; ++i) {
#pragma unroll
        for (int n = 0; n < 8; ++n) {
            const int row0 = mBase + i * 16 + (lane >> 2);
            const int col  = nBase + n * 8 + (lane & 3) * 2;
            float2* d0 = (float2*)(C + (size_t)row0 * FFN + col);
            float2* d1 = (float2*)(C + (size_t)(row0 + 8) * FFN + col);
            *d0 = make_float2(acc[i][n][0], acc[i][n][1]);
            *d1 = make_float2(acc[i][n][2], acc[i][n][3]);
        }
    }
}

// ================= launch =================

extern "C" void kernel_launch(void* const* d_in, const int* in_sizes, int n_in,
                              void* d_out, int out_size) {
    const float* A = (const float*)d_in[0];   // [16384, 2048]
    const float* W = (const float*)d_in[1];   // [8, 2048, 8192]
    float* C = (float*)d_out;                 // [16384, 8192]

    __half *Ah, *Wh;
    cudaGetSymbolAddress((void**)&Ah, g_Ah);
    cudaGetSymbolAddress((void**)&Wh, g_Wh);

    convA_kernel<<<(MTOTAL * HIDDEN) / (256 * 4), 256>>>(A, Ah);
    convW_kernel<<<(NGROUPS * HIDDEN * FFN) / (256 * 4), 256>>>(W, Wh);

    cudaFuncSetAttribute(gemm_hmma_kernel,
                         cudaFuncAttributeMaxDynamicSharedMemorySize, SMEM_DYN);
    const int totalCTAs = (MTOTAL / BM) * (FFN / BN);   // 4096
    for (int off = 0; off < totalCTAs; off += totalCTAs / 4)
        gemm_hmma_kernel<<<totalCTAs / 4, 256, SMEM_DYN>>>(C, off);
}

// round 9
// speedup vs baseline: 1.1084x; 1.1084x over previous
#include <cuda_runtime.h>
#include <cuda_fp16.h>
#include <cstdint>

// Grouped GEMM, pure fp16 HMMA, fp32 accumulate.
// B in native [k][n] layout, fragments via ldmatrix.trans.
// Tile 128x256, 512 threads (16 warps, warp tile 64x32), BK=64, 3-stage cp.async.

static constexpr int HIDDEN = 2048;
static constexpr int FFN    = 8192;
static constexpr int MTOTAL = 16384;
static constexpr int NGROUPS = 8;

#define BM 128
#define BN 256
#define BK 64
#define NTHREADS 512
static constexpr int NCHUNK = HIDDEN / BK;   // 32

// A row: 64 fp16 (128B) + 16B pad = 144B. B row: 256 fp16 (512B) + 16B pad = 528B.
#define ROWA 144
#define ROWBB 528
#define OFF_A 0
#define OFF_B (BM * ROWA)                    // 18432
#define STAGE (OFF_B + BK * ROWBB)           // 52224
#define NSTAGE 3
#define SMEM_DYN (NSTAGE * STAGE)            // 156672

// ---- scratch ----
__device__ __half g_Ah[(size_t)MTOTAL * HIDDEN];
__device__ __half g_Wh[(size_t)NGROUPS * HIDDEN * FFN];   // [g][k][n] native

__constant__ int kGroupOff[9] = {0, 1024, 2560, 4608, 6656, 9216, 11264, 14336, 16384};

__device__ __forceinline__ uint32_t pack_h2(__half lo, __half hi) {
    return (uint32_t)__half_as_ushort(lo) | ((uint32_t)__half_as_ushort(hi) << 16);
}

// ================= conversions (pure streaming) =================

__global__ void convA_kernel(const float* __restrict__ A, __half* __restrict__ Ah) {
    size_t i = ((size_t)blockIdx.x * blockDim.x + threadIdx.x) * 4;
    float4 v = *(const float4*)(A + i);
    ((uint32_t*)(Ah + i))[0] = pack_h2(__float2half(v.x), __float2half(v.y));
    ((uint32_t*)(Ah + i))[1] = pack_h2(__float2half(v.z), __float2half(v.w));
}

__global__ void convW_kernel(const float* __restrict__ W, __half* __restrict__ Wh) {
    size_t i = ((size_t)blockIdx.x * blockDim.x + threadIdx.x) * 4;
    float4 v = *(const float4*)(W + i);
    ((uint32_t*)(Wh + i))[0] = pack_h2(__float2half(v.x), __float2half(v.y));
    ((uint32_t*)(Wh + i))[1] = pack_h2(__float2half(v.z), __float2half(v.w));
}

// ================= GEMM =================

__device__ __forceinline__ uint32_t smem_u32(const void* p) {
    uint32_t a;
    asm("{ .reg .u64 t; cvta.to.shared.u64 t, %1; cvt.u32.u64 %0, t; }" : "=r"(a) : "l"(p));
    return a;
}
__device__ __forceinline__ void cp16(uint32_t dst, const void* src) {
    asm volatile("cp.async.cg.shared.global [%0], [%1], 16;\n"
                 :: "r"(dst), "l"(__cvta_generic_to_global(src)));
}
__device__ __forceinline__ void ldmx4(uint32_t* r, uint32_t addr) {
    asm volatile("ldmatrix.sync.aligned.m8n8.x4.shared.b16 {%0,%1,%2,%3}, [%4];"
                 : "=r"(r[0]), "=r"(r[1]), "=r"(r[2]), "=r"(r[3]) : "r"(addr));
}
__device__ __forceinline__ void ldmx4t(uint32_t* r, uint32_t addr) {
    asm volatile("ldmatrix.sync.aligned.m8n8.x4.trans.shared.b16 {%0,%1,%2,%3}, [%4];"
                 : "=r"(r[0]), "=r"(r[1]), "=r"(r[2]), "=r"(r[3]) : "r"(addr));
}
__device__ __forceinline__ void mma16816(float* c, const uint32_t* a, const uint32_t* b) {
    asm volatile(
        "mma.sync.aligned.m16n8k16.row.col.f32.f16.f16.f32 "
        "{%0,%1,%2,%3}, {%4,%5,%6,%7}, {%8,%9}, {%0,%1,%2,%3};"
        : "+f"(c[0]), "+f"(c[1]), "+f"(c[2]), "+f"(c[3])
        : "r"(a[0]), "r"(a[1]), "r"(a[2]), "r"(a[3]), "r"(b[0]), "r"(b[1]));
}

__global__ __launch_bounds__(NTHREADS, 1)
void gemm_hmma_kernel(float* __restrict__ C) {
    extern __shared__ char smem[];
    const uint32_t sb = smem_u32(smem);

    const int tid  = threadIdx.x;
    const int warp = tid >> 5;       // 0..15
    const int lane = tid & 31;
    const int warpM = warp & 1;      // 0..1 -> M offset *64
    const int warpN = warp >> 1;     // 0..7 -> N offset *32

    // panel swizzle: 16 m-tiles per panel, column sweep
    const int bid   = blockIdx.x;    // 0..4095
    const int panel = bid >> 9;
    const int idx   = bid & 511;
    const int rowBase = (panel * 16 + (idx & 15)) * BM;
    const int colBase = (idx >> 4) * BN;

    int g = 0;
#pragma unroll
    for (int i = 1; i < 8; ++i)
        if (rowBase >= kGroupOff[i]) g = i;

    const __half* pA = g_Ah + (size_t)rowBase * HIDDEN;
    const __half* pB = g_Wh + (size_t)g * HIDDEN * FFN + colBase;   // k-row major

    // A copy: 128 rows x 8 chunks = 1024 slots -> 2/thread
    const int arow = tid >> 3;          // 0..63 (+64i)
    const int achk = tid & 7;
    const uint32_t soA = (uint32_t)(arow * ROWA + achk * 16);
    const size_t   goA = (size_t)arow * HIDDEN + achk * 8;
    // B copy: 64 k-rows x 32 chunks = 2048 slots -> 4/thread
    const int brow = tid >> 5;          // 0..15 (+16i)
    const int bchk = tid & 31;
    const uint32_t soB = (uint32_t)(brow * ROWBB + bchk * 16);
    const size_t   goB = (size_t)brow * FFN + bchk * 8;

    // ldmatrix offsets
    const uint32_t aOff = (uint32_t)((warpM * 64 + (lane & 15)) * ROWA + (lane >> 4) * 16);
    uint32_t bOff[2];
#pragma unroll
    for (int t = 0; t < 2; ++t)
        bOff[t] = (uint32_t)((lane & 15) * ROWBB
                             + (warpN * 32 + t * 16 + 8 * (lane >> 4)) * 2);

    float acc[4][4][4];
#pragma unroll
    for (int i = 0; i < 4; ++i)
#pragma unroll
        for (int n = 0; n < 4; ++n)
#pragma unroll
            for (int q = 0; q < 4; ++q) acc[i][n][q] = 0.0f;

#define ISSUE_LOADS(stagep, jj)                                                \
    do {                                                                       \
        const uint32_t st_ = (stagep);                                         \
        const size_t koA_ = (size_t)(jj) * BK;                                 \
        const size_t koB_ = (size_t)(jj) * BK * FFN;                           \
        _Pragma("unroll")                                                      \
        for (int i_ = 0; i_ < 2; ++i_)                                         \
            cp16(st_ + OFF_A + soA + i_ * 64 * ROWA,                           \
                 pA + goA + (size_t)i_ * 64 * HIDDEN + koA_);                  \
        _Pragma("unroll")                                                      \
        for (int i_ = 0; i_ < 4; ++i_)                                         \
            cp16(st_ + OFF_B + soB + i_ * 16 * ROWBB,                          \
                 pB + goB + (size_t)i_ * 16 * FFN + koB_);                     \
    } while (0)

    // prologue
#pragma unroll
    for (int j = 0; j < NSTAGE - 1; ++j) {
        ISSUE_LOADS(sb + j * STAGE, j);
        asm volatile("cp.async.commit_group;" ::: "memory");
    }

    for (int j = 0; j < NCHUNK; ++j) {
        asm volatile("cp.async.wait_group %0;" :: "n"(NSTAGE - 2) : "memory");
        __syncthreads();

        if (j + NSTAGE - 1 < NCHUNK)
            ISSUE_LOADS(sb + ((j + NSTAGE - 1) % NSTAGE) * STAGE, j + NSTAGE - 1);
        asm volatile("cp.async.commit_group;" ::: "memory");

        const uint32_t st = sb + (j % NSTAGE) * STAGE;
#pragma unroll
        for (int s = 0; s < 4; ++s) {            // 4 k16-steps per BK=64
            uint32_t ah[4][4];
#pragma unroll
            for (int i = 0; i < 4; ++i)
                ldmx4(ah[i], st + OFF_A + aOff + i * 16 * ROWA + s * 32);
#pragma unroll
            for (int t = 0; t < 2; ++t) {
                uint32_t bh[4];
                ldmx4t(bh, st + OFF_B + bOff[t] + s * 16 * ROWBB);
#pragma unroll
                for (int i = 0; i < 4; ++i) {
                    mma16816(acc[i][2 * t],     ah[i], bh);
                    mma16816(acc[i][2 * t + 1], ah[i], bh + 2);
                }
            }
        }
    }
#undef ISSUE_LOADS

    // epilogue: warp tile 64x32
    const int mBase = rowBase + warpM * 64;
    const int nBase = colBase + warpN * 32;
#pragma unroll
    for (int i = 0; i < 4; ++i) {
#pragma unroll
        for (int n = 0; n < 4; ++n) {
            const int row0 = mBase + i * 16 + (lane >> 2);
            const int col  = nBase + n * 8 + (lane & 3) * 2;
            float2* d0 = (float2*)(C + (size_t)row0 * FFN + col);
            float2* d1 = (float2*)(C + (size_t)(row0 + 8) * FFN + col);
            *d0 = make_float2(acc[i][n][0], acc[i][n][1]);
            *d1 = make_float2(acc[i][n][2], acc[i][n][3]);
        }
    }
}

// ================= launch =================

extern "C" void kernel_launch(void* const* d_in, const int* in_sizes, int n_in,
                              void* d_out, int out_size) {
    const float* A = (const float*)d_in[0];   // [16384, 2048]
    const float* W = (const float*)d_in[1];   // [8, 2048, 8192]
    float* C = (float*)d_out;                 // [16384, 8192]

    __half *Ah, *Wh;
    cudaGetSymbolAddress((void**)&Ah, g_Ah);
    cudaGetSymbolAddress((void**)&Wh, g_Wh);

    convA_kernel<<<(MTOTAL * HIDDEN) / (256 * 4), 256>>>(A, Ah);
    convW_kernel<<<(NGROUPS * HIDDEN * FFN) / (256 * 4), 256>>>(W, Wh);

    cudaFuncSetAttribute(gemm_hmma_kernel,
                         cudaFuncAttributeMaxDynamicSharedMemorySize, SMEM_DYN);
    gemm_hmma_kernel<<<(MTOTAL / BM) * (FFN / BN), NTHREADS, SMEM_DYN>>>(C);
}